// round 5
// baseline (speedup 1.0000x reference)
#include <cuda_runtime.h>

#define NA      8192
#define DD      128
#define HH      256
#define ROWS_B  32
#define NC1     12          // cells per dimension (box 60 A / cutoff 5 A)
#define NCELL   (NC1*NC1*NC1)
#define MAXN    192         // max neighbors per atom (mean ~21)

typedef unsigned long long u64;

// Packed fp32x2 FMA — Blackwell FFMA2, only reachable via PTX fma.rn.f32x2
#define FMA2(d, a, b, c) \
    asm("fma.rn.f32x2 %0, %1, %2, %3;" : "=l"(d) : "l"(a), "l"(b), "l"(c))
#define PACK2(d, lo, hi) \
    asm("mov.b64 %0, {%1, %2};" : "=l"(d) : "f"(lo), "f"(hi))
#define UNPK2(lo, hi, s) \
    asm("mov.b64 {%0, %1}, %2;" : "=f"(lo), "=f"(hi) : "l"(s))

// Scratch (static __device__ — no allocation)
__device__ float4 g_pos4[NA];        // (x,y,z,s); s = |p|^2 ref-rounded
__device__ int    g_cellid[NA];
__device__ int    g_start[NCELL + 1];
__device__ int    g_slot[NA];        // cell-sorted original atom indices
__device__ float4 g_spos[NA];        // cell-sorted positions
__device__ int    g_stype[NA];       // cell-sorted types
__device__ float  g_feat[NA * 256];
__device__ float  g_partial[NA / ROWS_B];
__device__ int    g_done = 0;

// ---------------------------------------------------------------------------
// Prep: nm -> angstrom; s = ((x*x)+(y*y))+(z*z) with NO fma contraction
// (matches XLA's elementwise/reduce rounding). Also compute 5A cell id.
// ---------------------------------------------------------------------------
__global__ void k_prep(const float* __restrict__ pos) {
    int i = blockIdx.x * 256 + threadIdx.x;
    if (i < NA) {
        float x = __fmul_rn(10.0f, pos[3 * i + 0]);
        float y = __fmul_rn(10.0f, pos[3 * i + 1]);
        float z = __fmul_rn(10.0f, pos[3 * i + 2]);
        float s = __fadd_rn(__fadd_rn(__fmul_rn(x, x), __fmul_rn(y, y)),
                            __fmul_rn(z, z));
        g_pos4[i] = make_float4(x, y, z, s);
        int cx = min(NC1 - 1, max(0, (int)(x * 0.2f)));
        int cy = min(NC1 - 1, max(0, (int)(y * 0.2f)));
        int cz = min(NC1 - 1, max(0, (int)(z * 0.2f)));
        g_cellid[i] = (cz * NC1 + cy) * NC1 + cx;
    }
}

// ---------------------------------------------------------------------------
// Fused binning: histogram + prefix scan + scatter + per-cell sort + gather,
// all in ONE single-block kernel (1024 threads). Replaces 4 tiny launches.
// ---------------------------------------------------------------------------
__global__ void __launch_bounds__(1024) k_build(const int* __restrict__ types) {
    __shared__ int a[2048], b[2048];
    __shared__ int cur[NCELL];
    const int t = threadIdx.x;

    // phase 1: zero histogram
    if (t < NCELL - 1024) cur[1024 + t] = 0;
    cur[t] = 0;
    __syncthreads();

    // phase 2: count (each thread owns 8 atoms)
    int myc[8];
    #pragma unroll
    for (int k = 0; k < 8; k++) {
        myc[k] = g_cellid[t * 8 + k];
        atomicAdd(&cur[myc[k]], 1);
    }
    __syncthreads();

    // phase 3: inclusive Hillis-Steele scan over 2048-padded counts
    #pragma unroll
    for (int k = 0; k < 2; k++) {
        int idx = t + 1024 * k;
        a[idx] = (idx < NCELL) ? cur[idx] : 0;
    }
    __syncthreads();
    int* src = a; int* dst = b;
    for (int s = 1; s < 2048; s <<= 1) {
        #pragma unroll
        for (int k = 0; k < 2; k++) {
            int idx = t + 1024 * k;
            int v = src[idx];
            if (idx >= s) v += src[idx - s];
            dst[idx] = v;
        }
        __syncthreads();
        int* tmp = src; src = dst; dst = tmp;
    }

    // phase 4: start offsets + cursor init + sentinel
    #pragma unroll
    for (int k = 0; k < 2; k++) {
        int idx = t + 1024 * k;
        if (idx < NCELL) {
            int st = src[idx] - cur[idx];
            g_start[idx] = st;
            cur[idx] = st;
        }
    }
    if (t == 0) g_start[NCELL] = NA;
    __syncthreads();

    // phase 5: scatter (order arbitrary; sort below makes it deterministic)
    #pragma unroll
    for (int k = 0; k < 8; k++) {
        int slot = atomicAdd(&cur[myc[k]], 1);
        g_slot[slot] = t * 8 + k;
    }
    __syncthreads();

    // phase 6: per-cell insertion sort (deterministic order) + gather
    for (int c = t; c < NCELL; c += 1024) {
        int st = g_start[c], en = g_start[c + 1];
        for (int i = st + 1; i < en; i++) {
            int v = g_slot[i];
            int j = i - 1;
            while (j >= st && g_slot[j] > v) { g_slot[j + 1] = g_slot[j]; j--; }
            g_slot[j + 1] = v;
        }
        for (int i = st; i < en; i++) {
            int atom = g_slot[i];
            g_spos[i]  = g_pos4[atom];
            g_stype[i] = types[atom];
        }
    }
}

// ---------------------------------------------------------------------------
// Cell-list radius graph + sparse aggregation. 2 atoms / 256-thread block.
// 27 owner threads build a deterministic hit list (cell-major, atom-asc)
// via count pass + exclusive offset + write pass. Per-pair arithmetic is
// bit-identical to the reference:
//   dot = fma(z,z, fma(y,y, x*x));  d2 = RN(RN(s_i+s_j) - 2*dot)
// (noisy diagonal -> self-edges exactly as the dense reference produces)
// ---------------------------------------------------------------------------
__global__ void __launch_bounds__(256) k_agg(const float* __restrict__ emb) {
    __shared__ float s_phi [2][MAXN];
    __shared__ int   s_type[2][MAXN];
    __shared__ int   s_ccnt[2][27];
    __shared__ int   s_tot [2];

    const int t  = threadIdx.x;
    const int g  = t >> 7;
    const int tl = t & 127;
    const int bslot = blockIdx.x * 2 + g;    // sorted slot

    const float4 pi = g_spos[bslot];
    const int cx = min(NC1 - 1, max(0, (int)(pi.x * 0.2f)));
    const int cy = min(NC1 - 1, max(0, (int)(pi.y * 0.2f)));
    const int cz = min(NC1 - 1, max(0, (int)(pi.z * 0.2f)));

    // --- pass A: count hits per neighbor cell ---
    int nx = 0, ny = 0, nz = 0, valid = 0;
    if (tl < 27) {
        nx = cx + tl % 3 - 1;
        ny = cy + (tl / 3) % 3 - 1;
        nz = cz + tl / 9 - 1;
        valid = (nx >= 0) & (nx < NC1) & (ny >= 0) & (ny < NC1)
              & (nz >= 0) & (nz < NC1);
        int n = 0;
        if (valid) {
            int c  = (nz * NC1 + ny) * NC1 + nx;
            int st = g_start[c], en = g_start[c + 1];
            for (int k = st; k < en; k++) {
                float4 pj = g_spos[k];
                float dot = __fmul_rn(pi.x, pj.x);
                dot = fmaf(pi.y, pj.y, dot);
                dot = fmaf(pi.z, pj.z, dot);
                float t1 = __fadd_rn(pi.w, pj.w);
                float d2 = __fadd_rn(t1, __fmul_rn(-2.0f, dot));
                if (d2 > 1e-12f) {
                    float d = __fsqrt_rn(d2);
                    if (d <= 5.0f) n++;
                }
            }
        }
        s_ccnt[g][tl] = n;
    }
    __syncthreads();

    // --- pass B: exclusive offset, recompute + write hits ---
    if (tl < 27) {
        int off = 0;
        #pragma unroll 1
        for (int q = 0; q < tl; q++) off += s_ccnt[g][q];
        if (tl == 26) s_tot[g] = off + s_ccnt[g][26];
        if (valid) {
            int c  = (nz * NC1 + ny) * NC1 + nx;
            int st = g_start[c], en = g_start[c + 1];
            for (int k = st; k < en; k++) {
                float4 pj = g_spos[k];
                float dot = __fmul_rn(pi.x, pj.x);
                dot = fmaf(pi.y, pj.y, dot);
                dot = fmaf(pi.z, pj.z, dot);
                float t1 = __fadd_rn(pi.w, pj.w);
                float d2 = __fadd_rn(t1, __fmul_rn(-2.0f, dot));
                if (d2 > 1e-12f) {
                    float d = __fsqrt_rn(d2);
                    if (d <= 5.0f && off < MAXN) {
                        s_phi [g][off] = expf(-d);
                        s_type[g][off] = g_stype[k];
                        off++;
                    }
                }
            }
        }
    }
    __syncthreads();

    // --- 128 feature threads drain the hit list ---
    float acc = 0.0f;
    const int tot = s_tot[g];
    #pragma unroll 4
    for (int e = 0; e < tot; e++)
        acc = fmaf(s_phi[g][e], emb[s_type[g][e] * DD + tl], acc);

    const int i = g_slot[bslot];                 // original atom index
    g_feat[i * 256 + tl]       = emb[g_stype[bslot] * DD + tl];  // h_i
    g_feat[i * 256 + 128 + tl] = acc;                             // agg_i
}

// ---------------------------------------------------------------------------
// MLP + fused final reduce. e_node = relu(feat @ W1) @ w2.
// Inner product on packed fp32x2 (FFMA2): even/odd k-pairs in the two lanes,
// combined (lo+hi) before the relu. 256 threads = hidden units, 32 rows/blk.
// Last finishing block reduces the 256 partials in fixed tree order.
// ---------------------------------------------------------------------------
__global__ void __launch_bounds__(256, 2) k_mlp(const float* __restrict__ W1,
                                                const float* __restrict__ w2,
                                                float* __restrict__ out) {
    __shared__ float s_feat[ROWS_B * 256];
    __shared__ float s_red[256];
    __shared__ int   s_last;

    const int u    = threadIdx.x;
    const int row0 = blockIdx.x * ROWS_B;

    {   // cooperative vectorized load of ROWS_B contiguous feature rows
        const float4* src = (const float4*)(g_feat + row0 * 256);
        float4*       dst = (float4*)s_feat;
        #pragma unroll
        for (int k = 0; k < (ROWS_B * 64) / 256; k++)
            dst[k * 256 + u] = src[k * 256 + u];
    }
    __syncthreads();

    u64 acc2[ROWS_B];
    #pragma unroll
    for (int r = 0; r < ROWS_B; r++) acc2[r] = 0ull;   // (0.0f, 0.0f)

    #pragma unroll 1
    for (int kk = 0; kk < 2 * DD; kk += 16) {
        u64 wp[8];
        #pragma unroll
        for (int m = 0; m < 8; m++) {
            float wlo = W1[(kk + 2 * m)     * HH + u];
            float whi = W1[(kk + 2 * m + 1) * HH + u];
            PACK2(wp[m], wlo, whi);
        }
        #pragma unroll
        for (int r = 0; r < ROWS_B; r++) {
            const ulonglong2* fp =
                (const ulonglong2*)(s_feat + r * 256 + kk);   // warp-uniform
            #pragma unroll
            for (int q = 0; q < 4; q++) {
                ulonglong2 fv = fp[q];
                FMA2(acc2[r], fv.x, wp[2 * q],     acc2[r]);
                FMA2(acc2[r], fv.y, wp[2 * q + 1], acc2[r]);
            }
        }
    }

    float p = 0.0f;
    #pragma unroll
    for (int r = 0; r < ROWS_B; r++) {
        float lo, hi;
        UNPK2(lo, hi, acc2[r]);
        p += fmaxf(lo + hi, 0.0f);
    }
    p *= w2[u];

    s_red[u] = p;
    __syncthreads();
    for (int s = 128; s > 0; s >>= 1) {
        if (u < s) s_red[u] += s_red[u + s];
        __syncthreads();
    }
    if (u == 0) g_partial[blockIdx.x] = s_red[0];

    // --- last block performs the deterministic final reduction ---
    __threadfence();
    if (u == 0) s_last = (atomicAdd(&g_done, 1) == gridDim.x - 1);
    __syncthreads();
    if (s_last) {
        __threadfence();
        s_red[u] = *((volatile float*)g_partial + u);
        __syncthreads();
        for (int s = 128; s > 0; s >>= 1) {
            if (u < s) s_red[u] += s_red[u + s];
            __syncthreads();
        }
        if (u == 0) {
            out[0] = s_red[0] * 0.2390057361376673f;   // kJ/mol -> kcal/mol
            g_done = 0;                                 // reset for replay
        }
    }
}

// ---------------------------------------------------------------------------
extern "C" void kernel_launch(void* const* d_in, const int* in_sizes, int n_in,
                              void* d_out, int out_size) {
    const float* pos   = (const float*)d_in[0];
    const int*   types = (const int*)d_in[1];
    const float* emb   = (const float*)d_in[2];
    const float* W1    = (const float*)d_in[3];
    const float* w2    = (const float*)d_in[4];
    float*       out   = (float*)d_out;

    k_prep <<<NA / 256, 256>>>(pos);
    k_build<<<1, 1024>>>(types);
    k_agg  <<<NA / 2, 256>>>(emb);
    k_mlp  <<<NA / ROWS_B, 256>>>(W1, w2, out);
}

// round 6
// speedup vs baseline: 1.0548x; 1.0548x over previous
#include <cuda_runtime.h>

#define NA      8192
#define DD      128
#define HH      256
#define NC1     12          // cells per dimension (box 60 A / cutoff 5 A)
#define NCELL   (NC1*NC1*NC1)
#define MAXC    384         // max candidate atoms in 27 cells (mean ~128)
#define MAXN    96          // max hits per atom (mean ~21)
#define BM      64
#define BN      64
#define BK      16
#define NBLK_M  ((NA/BM)*(HH/BN))   // 128*4 = 512 mlp blocks

typedef unsigned long long u64;

// Packed fp32x2 FMA — Blackwell FFMA2, only reachable via PTX fma.rn.f32x2
#define FMA2(d, a, b, c) \
    asm("fma.rn.f32x2 %0, %1, %2, %3;" : "=l"(d) : "l"(a), "l"(b), "l"(c))
#define PACK2(d, lo, hi) \
    asm("mov.b64 %0, {%1, %2};" : "=l"(d) : "f"(lo), "f"(hi))
#define UNPK2(lo, hi, s) \
    asm("mov.b64 {%0, %1}, %2;" : "=f"(lo), "=f"(hi) : "l"(s))

// Scratch (static __device__ — no allocation)
__device__ float4 g_pos4[NA];        // (x,y,z,s); s = |p|^2 ref-rounded
__device__ int    g_cellid[NA];
__device__ int    g_start[NCELL + 1];
__device__ int    g_slot[NA];        // cell-sorted original atom indices
__device__ float4 g_spos[NA];        // cell-sorted positions
__device__ int    g_stype[NA];       // cell-sorted types
__device__ float  g_feat[NA * 256];
__device__ float  g_partial[NBLK_M];
__device__ int    g_done = 0;

// ---------------------------------------------------------------------------
// Prep: nm -> angstrom; s = ((x*x)+(y*y))+(z*z) with NO fma contraction
// (matches XLA's elementwise/reduce rounding). Also compute 5A cell id.
// ---------------------------------------------------------------------------
__global__ void k_prep(const float* __restrict__ pos) {
    int i = blockIdx.x * 256 + threadIdx.x;
    if (i < NA) {
        float x = __fmul_rn(10.0f, pos[3 * i + 0]);
        float y = __fmul_rn(10.0f, pos[3 * i + 1]);
        float z = __fmul_rn(10.0f, pos[3 * i + 2]);
        float s = __fadd_rn(__fadd_rn(__fmul_rn(x, x), __fmul_rn(y, y)),
                            __fmul_rn(z, z));
        g_pos4[i] = make_float4(x, y, z, s);
        int cx = min(NC1 - 1, max(0, (int)(x * 0.2f)));
        int cy = min(NC1 - 1, max(0, (int)(y * 0.2f)));
        int cz = min(NC1 - 1, max(0, (int)(z * 0.2f)));
        g_cellid[i] = (cz * NC1 + cy) * NC1 + cx;
    }
}

// ---------------------------------------------------------------------------
// Fused binning: histogram + scan + scatter + per-cell sort + gather,
// one single-block kernel (1024 threads).
// ---------------------------------------------------------------------------
__global__ void __launch_bounds__(1024) k_build(const int* __restrict__ types) {
    __shared__ int a[2048], b[2048];
    __shared__ int cur[NCELL];
    const int t = threadIdx.x;

    if (t < NCELL - 1024) cur[1024 + t] = 0;
    cur[t] = 0;
    __syncthreads();

    int myc[8];
    #pragma unroll
    for (int k = 0; k < 8; k++) {
        myc[k] = g_cellid[t * 8 + k];
        atomicAdd(&cur[myc[k]], 1);
    }
    __syncthreads();

    #pragma unroll
    for (int k = 0; k < 2; k++) {
        int idx = t + 1024 * k;
        a[idx] = (idx < NCELL) ? cur[idx] : 0;
    }
    __syncthreads();
    int* src = a; int* dst = b;
    for (int s = 1; s < 2048; s <<= 1) {
        #pragma unroll
        for (int k = 0; k < 2; k++) {
            int idx = t + 1024 * k;
            int v = src[idx];
            if (idx >= s) v += src[idx - s];
            dst[idx] = v;
        }
        __syncthreads();
        int* tmp = src; src = dst; dst = tmp;
    }

    #pragma unroll
    for (int k = 0; k < 2; k++) {
        int idx = t + 1024 * k;
        if (idx < NCELL) {
            int st = src[idx] - cur[idx];
            g_start[idx] = st;
            cur[idx] = st;
        }
    }
    if (t == 0) g_start[NCELL] = NA;
    __syncthreads();

    #pragma unroll
    for (int k = 0; k < 8; k++) {
        int slot = atomicAdd(&cur[myc[k]], 1);
        g_slot[slot] = t * 8 + k;
    }
    __syncthreads();

    for (int c = t; c < NCELL; c += 1024) {
        int st = g_start[c], en = g_start[c + 1];
        for (int i = st + 1; i < en; i++) {
            int v = g_slot[i];
            int j = i - 1;
            while (j >= st && g_slot[j] > v) { g_slot[j + 1] = g_slot[j]; j--; }
            g_slot[j + 1] = v;
        }
        for (int i = st; i < en; i++) {
            int atom = g_slot[i];
            g_spos[i]  = g_pos4[atom];
            g_stype[i] = types[atom];
        }
    }
}

// ---------------------------------------------------------------------------
// Cell-list radius graph + sparse aggregation. ONE atom per 128-thread block.
// Owners (tl<27) emit a candidate list (cell-major, slot-ascending); all 128
// threads test candidates in parallel (one pass); hits compacted with a
// deterministic ballot + cross-warp scan, preserving candidate order exactly
// (same summation order as rounds 3/4). Per-pair arithmetic bit-identical
// to the reference:
//   dot = fma(z,z, fma(y,y, x*x));  d2 = RN(RN(s_i+s_j) - 2*dot)
// ---------------------------------------------------------------------------
__global__ void __launch_bounds__(128) k_agg(const float* __restrict__ emb) {
    __shared__ int   s_cand[MAXC];
    __shared__ float s_phi [MAXN];
    __shared__ int   s_type[MAXN];
    __shared__ int   s_ccnt[27];
    __shared__ int   s_cst [27];
    __shared__ int   s_wc  [4];
    __shared__ int   s_ncand;

    const int tl    = threadIdx.x;
    const int bslot = blockIdx.x;          // sorted slot

    const float4 pi = g_spos[bslot];
    const int cx = min(NC1 - 1, max(0, (int)(pi.x * 0.2f)));
    const int cy = min(NC1 - 1, max(0, (int)(pi.y * 0.2f)));
    const int cz = min(NC1 - 1, max(0, (int)(pi.z * 0.2f)));

    // --- owners: neighbor-cell extents ---
    if (tl < 27) {
        int nx = cx + tl % 3 - 1;
        int ny = cy + (tl / 3) % 3 - 1;
        int nz = cz + tl / 9 - 1;
        int valid = (nx >= 0) & (nx < NC1) & (ny >= 0) & (ny < NC1)
                  & (nz >= 0) & (nz < NC1);
        int st = 0, cnt = 0;
        if (valid) {
            int c = (nz * NC1 + ny) * NC1 + nx;
            st  = g_start[c];
            cnt = g_start[c + 1] - st;
        }
        s_cst[tl]  = st;
        s_ccnt[tl] = cnt;
    }
    __syncthreads();

    // --- owners: fill candidate list in deterministic cell-major order ---
    if (tl < 27) {
        int off = 0;
        #pragma unroll 1
        for (int q = 0; q < tl; q++) off += s_ccnt[q];
        int cnt = s_ccnt[tl], st = s_cst[tl];
        if (tl == 26) s_ncand = off + cnt;
        for (int q = 0; q < cnt && off + q < MAXC; q++)
            s_cand[off + q] = st + q;
    }
    __syncthreads();

    // --- all 128 threads test candidates; deterministic compaction ---
    const int ncand = s_ncand;
    int nh = 0;
    const int wid = tl >> 5, lane = tl & 31;
    const unsigned lmask = (1u << lane) - 1u;

    for (int base = 0; base < ncand; base += 128) {
        int idx  = base + tl;
        int pred = 0, typ = 0;
        float phi = 0.0f;
        if (idx < ncand) {
            int k = s_cand[idx];
            float4 pj = g_spos[k];
            float dot = __fmul_rn(pi.x, pj.x);
            dot = fmaf(pi.y, pj.y, dot);
            dot = fmaf(pi.z, pj.z, dot);
            float t1 = __fadd_rn(pi.w, pj.w);
            float d2 = __fadd_rn(t1, __fmul_rn(-2.0f, dot));
            if (d2 > 1e-12f) {
                float d = __fsqrt_rn(d2);
                if (d <= 5.0f) {
                    pred = 1;
                    phi  = expf(-d);
                    typ  = g_stype[k];
                }
            }
        }
        unsigned m = __ballot_sync(0xffffffffu, pred);
        if (lane == 0) s_wc[wid] = __popc(m);
        __syncthreads();
        int woff = 0;
        #pragma unroll
        for (int w = 0; w < 4; w++) if (w < wid) woff += s_wc[w];
        if (pred) {
            int pos = nh + woff + __popc(m & lmask);
            if (pos < MAXN) { s_phi[pos] = phi; s_type[pos] = typ; }
        }
        nh += s_wc[0] + s_wc[1] + s_wc[2] + s_wc[3];
        __syncthreads();
    }

    // --- drain: thread tl owns feature component tl ---
    float acc = 0.0f;
    #pragma unroll 4
    for (int e = 0; e < nh; e++)
        acc = fmaf(s_phi[e], emb[s_type[e] * DD + tl], acc);

    const int i = g_slot[bslot];                         // original atom index
    g_feat[i * 256 + tl]       = emb[g_stype[bslot] * DD + tl];  // h_i
    g_feat[i * 256 + 128 + tl] = acc;                             // agg_i
}

// ---------------------------------------------------------------------------
// Register-blocked GEMM MLP on FFMA2 + fused deterministic final reduce.
// Block = 64 rows x 64 cols tile; 256 threads; thread = 4x4 micro-tile with
// accumulator lanes = two adjacent output columns (W1 pairs natural from
// LDS.128; feat pre-duplicated (v,v) in smem so no packing in hot loop).
// ---------------------------------------------------------------------------
__global__ void __launch_bounds__(256) k_mlp(const float* __restrict__ W1,
                                             const float* __restrict__ w2,
                                             float* __restrict__ out) {
    __shared__ u64   s_f2[BK][BM + 2];   // dup feat, padded vs bank conflicts
    __shared__ float s_w [BK][BN];
    __shared__ float s_red[256];
    __shared__ int   s_last;

    const int u  = threadIdx.x;
    const int tx = u & 15, ty = u >> 4;
    const int row0 = (blockIdx.x & 127) * BM;
    const int c0   = (blockIdx.x >> 7) * BN;

    const int frow = u >> 2;            // 0..63 : feat row to stage
    const int fkq  = (u & 3) * 4;       // k-offset within chunk
    const int wk   = u >> 4;            // 0..15 : W1 k-row to stage
    const int wc   = (u & 15) * 4;      // col offset

    u64 acc[4][2];
    #pragma unroll
    for (int r = 0; r < 4; r++) { acc[r][0] = 0ull; acc[r][1] = 0ull; }

    #pragma unroll 1
    for (int kk = 0; kk < 2 * DD; kk += BK) {
        float4 f  = *(const float4*)(g_feat + (row0 + frow) * 256 + kk + fkq);
        float4 wv = *(const float4*)(W1 + (kk + wk) * HH + c0 + wc);
        __syncthreads();
        u64 d0, d1, d2d, d3;
        PACK2(d0, f.x, f.x); PACK2(d1, f.y, f.y);
        PACK2(d2d, f.z, f.z); PACK2(d3, f.w, f.w);
        s_f2[fkq + 0][frow] = d0;
        s_f2[fkq + 1][frow] = d1;
        s_f2[fkq + 2][frow] = d2d;
        s_f2[fkq + 3][frow] = d3;
        *(float4*)&s_w[wk][wc] = wv;
        __syncthreads();

        #pragma unroll
        for (int k = 0; k < BK; k++) {
            ulonglong2 fa = *(const ulonglong2*)&s_f2[k][ty * 4];
            ulonglong2 fb = *(const ulonglong2*)&s_f2[k][ty * 4 + 2];
            ulonglong2 wp = *(const ulonglong2*)&s_w[k][tx * 4];
            FMA2(acc[0][0], fa.x, wp.x, acc[0][0]);
            FMA2(acc[0][1], fa.x, wp.y, acc[0][1]);
            FMA2(acc[1][0], fa.y, wp.x, acc[1][0]);
            FMA2(acc[1][1], fa.y, wp.y, acc[1][1]);
            FMA2(acc[2][0], fb.x, wp.x, acc[2][0]);
            FMA2(acc[2][1], fb.x, wp.y, acc[2][1]);
            FMA2(acc[3][0], fb.y, wp.x, acc[3][0]);
            FMA2(acc[3][1], fb.y, wp.y, acc[3][1]);
        }
    }

    // epilogue: relu, * w2, sum thread's 16 outputs
    float4 w2v = *(const float4*)(w2 + c0 + tx * 4);
    float p = 0.0f;
    #pragma unroll
    for (int r = 0; r < 4; r++) {
        float lo, hi;
        UNPK2(lo, hi, acc[r][0]);
        p += fmaxf(lo, 0.0f) * w2v.x + fmaxf(hi, 0.0f) * w2v.y;
        UNPK2(lo, hi, acc[r][1]);
        p += fmaxf(lo, 0.0f) * w2v.z + fmaxf(hi, 0.0f) * w2v.w;
    }

    s_red[u] = p;
    __syncthreads();
    for (int s = 128; s > 0; s >>= 1) {
        if (u < s) s_red[u] += s_red[u + s];
        __syncthreads();
    }
    if (u == 0) g_partial[blockIdx.x] = s_red[0];

    // --- last block: deterministic final reduction over 512 partials ---
    __threadfence();
    if (u == 0) s_last = (atomicAdd(&g_done, 1) == gridDim.x - 1);
    __syncthreads();
    if (s_last) {
        __threadfence();
        volatile float* gp = (volatile float*)g_partial;
        s_red[u] = gp[u] + gp[u + 256];
        __syncthreads();
        for (int s = 128; s > 0; s >>= 1) {
            if (u < s) s_red[u] += s_red[u + s];
            __syncthreads();
        }
        if (u == 0) {
            out[0] = s_red[0] * 0.2390057361376673f;   // kJ/mol -> kcal/mol
            g_done = 0;                                 // reset for replay
        }
    }
}

// ---------------------------------------------------------------------------
extern "C" void kernel_launch(void* const* d_in, const int* in_sizes, int n_in,
                              void* d_out, int out_size) {
    const float* pos   = (const float*)d_in[0];
    const int*   types = (const int*)d_in[1];
    const float* emb   = (const float*)d_in[2];
    const float* W1    = (const float*)d_in[3];
    const float* w2    = (const float*)d_in[4];
    float*       out   = (float*)d_out;

    k_prep <<<NA / 256, 256>>>(pos);
    k_build<<<1, 1024>>>(types);
    k_agg  <<<NA, 128>>>(emb);
    k_mlp  <<<NBLK_M, 256>>>(W1, w2, out);
}

// round 7
// speedup vs baseline: 1.1966x; 1.1345x over previous
#include <cuda_runtime.h>

#define NA      8192
#define DD      128
#define HH      256
#define NC1     12          // cells per dimension (box 60 A / cutoff 5 A)
#define NCELL   (NC1*NC1*NC1)
#define MAXC    512         // max candidate atoms across 27 cells
#define MAXN    96          // max hits per atom (mean ~21)
#define RB      32          // rows per mlp block
#define NBLK_M  (NA / RB)   // 256

typedef unsigned long long u64;

// Packed fp32x2 FMA — Blackwell FFMA2, only reachable via PTX fma.rn.f32x2
#define FMA2(d, a, b, c) \
    asm("fma.rn.f32x2 %0, %1, %2, %3;" : "=l"(d) : "l"(a), "l"(b), "l"(c))
#define PACK2(d, lo, hi) \
    asm("mov.b64 %0, {%1, %2};" : "=l"(d) : "f"(lo), "f"(hi))
#define UNPK2(lo, hi, s) \
    asm("mov.b64 {%0, %1}, %2;" : "=f"(lo), "=f"(hi) : "l"(s))

// Scratch (static __device__ — no allocation)
__device__ float4 g_pos4[NA];        // (x,y,z,s); s = |p|^2 ref-rounded
__device__ int    g_cellid[NA];
__device__ int    g_start[NCELL + 1];
__device__ int    g_slot[NA];        // cell-sorted original atom indices
__device__ float  g_feat[NA * 256];
__device__ float  g_partial[NBLK_M];
__device__ int    g_done = 0;

// ---------------------------------------------------------------------------
// Prep: nm -> angstrom; s = ((x*x)+(y*y))+(z*z) with NO fma contraction
// (matches XLA's elementwise/reduce rounding). Also compute 5A cell id.
// ---------------------------------------------------------------------------
__global__ void k_prep(const float* __restrict__ pos) {
    int i = blockIdx.x * 256 + threadIdx.x;
    if (i < NA) {
        float x = __fmul_rn(10.0f, pos[3 * i + 0]);
        float y = __fmul_rn(10.0f, pos[3 * i + 1]);
        float z = __fmul_rn(10.0f, pos[3 * i + 2]);
        float s = __fadd_rn(__fadd_rn(__fmul_rn(x, x), __fmul_rn(y, y)),
                            __fmul_rn(z, z));
        g_pos4[i] = make_float4(x, y, z, s);
        int cx = min(NC1 - 1, max(0, (int)(x * 0.2f)));
        int cy = min(NC1 - 1, max(0, (int)(y * 0.2f)));
        int cz = min(NC1 - 1, max(0, (int)(z * 0.2f)));
        g_cellid[i] = (cz * NC1 + cy) * NC1 + cx;
    }
}

// ---------------------------------------------------------------------------
// Binning: histogram + scan + scatter + per-cell sort of slot indices.
// Single block, 1024 threads. No gather (k_agg stages via g_slot).
// ---------------------------------------------------------------------------
__global__ void __launch_bounds__(1024) k_build() {
    __shared__ int a[2048], b[2048];
    __shared__ int cur[NCELL];
    const int t = threadIdx.x;

    if (t < NCELL - 1024) cur[1024 + t] = 0;
    cur[t] = 0;
    __syncthreads();

    int myc[8];
    #pragma unroll
    for (int k = 0; k < 8; k++) {
        myc[k] = g_cellid[t * 8 + k];
        atomicAdd(&cur[myc[k]], 1);
    }
    __syncthreads();

    #pragma unroll
    for (int k = 0; k < 2; k++) {
        int idx = t + 1024 * k;
        a[idx] = (idx < NCELL) ? cur[idx] : 0;
    }
    __syncthreads();
    int* src = a; int* dst = b;
    for (int s = 1; s < 2048; s <<= 1) {
        #pragma unroll
        for (int k = 0; k < 2; k++) {
            int idx = t + 1024 * k;
            int v = src[idx];
            if (idx >= s) v += src[idx - s];
            dst[idx] = v;
        }
        __syncthreads();
        int* tmp = src; src = dst; dst = tmp;
    }

    #pragma unroll
    for (int k = 0; k < 2; k++) {
        int idx = t + 1024 * k;
        if (idx < NCELL) {
            int st = src[idx] - cur[idx];
            g_start[idx] = st;
            cur[idx] = st;
        }
    }
    if (t == 0) g_start[NCELL] = NA;
    __syncthreads();

    #pragma unroll
    for (int k = 0; k < 8; k++) {
        int slot = atomicAdd(&cur[myc[k]], 1);
        g_slot[slot] = t * 8 + k;
    }
    __syncthreads();

    // per-cell insertion sort of slots (deterministic atom order)
    for (int c = t; c < NCELL; c += 1024) {
        int st = g_start[c], en = g_start[c + 1];
        for (int i = st + 1; i < en; i++) {
            int v = g_slot[i];
            int j = i - 1;
            while (j >= st && g_slot[j] > v) { g_slot[j + 1] = g_slot[j]; j--; }
            g_slot[j + 1] = v;
        }
    }
}

// ---------------------------------------------------------------------------
// Per-CELL radius graph + aggregation. Block = one cell, 128 threads.
// Candidate set (27 neighbor cells, cell-major by (dz,dy,dx), slot-ascending
// within cell — IDENTICAL order to previous rounds) staged ONCE into smem and
// reused for every home atom. Per home atom: parallel test + deterministic
// ballot compaction + drain. Per-pair arithmetic bit-identical to reference:
//   dot = fma(z,z, fma(y,y, x*x));  d2 = RN(RN(s_i+s_j) - 2*dot)
// ---------------------------------------------------------------------------
__global__ void __launch_bounds__(128) k_agg(const float* __restrict__ emb,
                                             const int* __restrict__ types) {
    __shared__ float4 s_cpos[MAXC];
    __shared__ int    s_ctyp[MAXC];
    __shared__ float  s_phi [MAXN];
    __shared__ int    s_typ [MAXN];
    __shared__ int    s_gst [27];
    __shared__ int    s_coff[28];
    __shared__ int    s_wc  [4];

    const int tl = threadIdx.x;
    const int c  = blockIdx.x;
    const int cx = c % NC1, cy = (c / NC1) % NC1, cz = c / (NC1 * NC1);

    // --- neighbor-cell extents (deterministic cell-major order) ---
    if (tl < 27) {
        int nx = cx + tl % 3 - 1;
        int ny = cy + (tl / 3) % 3 - 1;
        int nz = cz + tl / 9 - 1;
        int valid = (nx >= 0) & (nx < NC1) & (ny >= 0) & (ny < NC1)
                  & (nz >= 0) & (nz < NC1);
        int st = 0, cnt = 0;
        if (valid) {
            int nc = (nz * NC1 + ny) * NC1 + nx;
            st  = g_start[nc];
            cnt = g_start[nc + 1] - st;
        }
        s_gst[tl]  = st;
        s_coff[tl] = cnt;          // temporarily counts
    }
    __syncthreads();
    if (tl == 0) {                 // tiny serial prefix (27 elems, once/block)
        int run = 0;
        #pragma unroll 1
        for (int q = 0; q < 27; q++) {
            int v = s_coff[q];
            s_coff[q] = run;
            run += v;
        }
        s_coff[27] = run;
    }
    __syncthreads();

    const int ncand = s_coff[27];

    // --- parallel candidate staging (one dependent-load round) ---
    for (int p = tl; p < ncand; p += 128) {
        int q = 0;
        while (s_coff[q + 1] <= p) q++;
        int slot = s_gst[q] + (p - s_coff[q]);
        int a    = g_slot[slot];
        s_cpos[p] = g_pos4[a];
        s_ctyp[p] = types[a];
    }
    __syncthreads();

    const int hbase = s_coff[13];              // center cell (dx=dy=dz=0)
    const int nhome = s_coff[14] - s_coff[13];
    const int hst   = s_gst[13];
    const int wid = tl >> 5, lane = tl & 31;
    const unsigned lmask = (1u << lane) - 1u;

    for (int ha = 0; ha < nhome; ha++) {
        const float4 pi = s_cpos[hbase + ha];

        int nh = 0;
        for (int base = 0; base < ncand; base += 128) {
            int idx  = base + tl;
            int pred = 0, typ = 0;
            float phi = 0.0f;
            if (idx < ncand) {
                float4 pj = s_cpos[idx];
                float dot = __fmul_rn(pi.x, pj.x);
                dot = fmaf(pi.y, pj.y, dot);
                dot = fmaf(pi.z, pj.z, dot);
                float t1 = __fadd_rn(pi.w, pj.w);
                float d2 = __fadd_rn(t1, __fmul_rn(-2.0f, dot));
                if (d2 > 1e-12f) {
                    float d = __fsqrt_rn(d2);
                    if (d <= 5.0f) {
                        pred = 1;
                        phi  = expf(-d);
                        typ  = s_ctyp[idx];
                    }
                }
            }
            unsigned m = __ballot_sync(0xffffffffu, pred);
            if (lane == 0) s_wc[wid] = __popc(m);
            __syncthreads();
            int woff = 0;
            #pragma unroll
            for (int w = 0; w < 4; w++) if (w < wid) woff += s_wc[w];
            if (pred) {
                int posn = nh + woff + __popc(m & lmask);
                if (posn < MAXN) { s_phi[posn] = phi; s_typ[posn] = typ; }
            }
            nh += s_wc[0] + s_wc[1] + s_wc[2] + s_wc[3];
            __syncthreads();
        }

        // drain: thread tl owns feature component tl
        float acc = 0.0f;
        #pragma unroll 4
        for (int e = 0; e < nh; e++)
            acc = fmaf(s_phi[e], emb[s_typ[e] * DD + tl], acc);

        const int i = g_slot[hst + ha];                       // original index
        g_feat[i * 256 + tl]       = emb[s_ctyp[hbase + ha] * DD + tl];
        g_feat[i * 256 + 128 + tl] = acc;
        __syncthreads();               // s_phi reuse guard for next home atom
    }
}

// ---------------------------------------------------------------------------
// MLP on FFMA2 with broadcast feat. Thread u = hidden unit (W1 column),
// RB=32 rows/block staged transposed as row-pair u64s s_ft[rp][k] so every
// hot-loop LDS is warp-uniform -> broadcast (crossbar ~free). W1 pairs (w,w)
// in registers. Each FFMA2 lane = independent sequential-k chain (same
// rounding as scalar fma chain). Fused deterministic last-block reduce.
// ---------------------------------------------------------------------------
__global__ void __launch_bounds__(256) k_mlp(const float* __restrict__ W1,
                                             const float* __restrict__ w2,
                                             float* __restrict__ out) {
    __shared__ u64   s_ft[(RB / 2) * 256];    // [rp][k], 32 KB
    __shared__ float s_red[256];
    __shared__ int   s_last;

    const int u    = threadIdx.x;
    const int row0 = blockIdx.x * RB;

    {   // stage + transpose: rows (coalesced float4) -> row-pair float pairs
        const float4* src = (const float4*)(g_feat + row0 * 256);
        float*        dstf = (float*)s_ft;
        #pragma unroll
        for (int j = 0; j < (RB * 64) / 256; j++) {
            int idx = u + 256 * j;             // float4 index
            int row = idx >> 6;
            int kq  = (idx & 63) << 2;
            float4 f = src[idx];
            int b = (row >> 1) * 512 + (row & 1);
            dstf[b + 2 * (kq + 0)] = f.x;
            dstf[b + 2 * (kq + 1)] = f.y;
            dstf[b + 2 * (kq + 2)] = f.z;
            dstf[b + 2 * (kq + 3)] = f.w;
        }
    }
    __syncthreads();

    u64 acc2[RB / 2];
    #pragma unroll
    for (int rp = 0; rp < RB / 2; rp++) acc2[rp] = 0ull;

    #pragma unroll 1
    for (int kk = 0; kk < 2 * DD; kk += 16) {
        u64 wd[16];
        #pragma unroll
        for (int m = 0; m < 16; m++) {
            float w = W1[(kk + m) * HH + u];   // coalesced
            PACK2(wd[m], w, w);
        }
        #pragma unroll
        for (int rp = 0; rp < RB / 2; rp++) {
            const ulonglong2* fp =
                (const ulonglong2*)(s_ft + rp * 256 + kk);   // warp-uniform
            #pragma unroll
            for (int q = 0; q < 8; q++) {
                ulonglong2 v = fp[q];                         // broadcast LDS
                FMA2(acc2[rp], v.x, wd[2 * q],     acc2[rp]);
                FMA2(acc2[rp], v.y, wd[2 * q + 1], acc2[rp]);
            }
        }
    }

    // epilogue: relu both row-lanes, sum, * w2[u]
    float p = 0.0f;
    #pragma unroll
    for (int rp = 0; rp < RB / 2; rp++) {
        float lo, hi;
        UNPK2(lo, hi, acc2[rp]);
        p += fmaxf(lo, 0.0f) + fmaxf(hi, 0.0f);
    }
    p *= w2[u];

    s_red[u] = p;
    __syncthreads();
    for (int s = 128; s > 0; s >>= 1) {
        if (u < s) s_red[u] += s_red[u + s];
        __syncthreads();
    }
    if (u == 0) g_partial[blockIdx.x] = s_red[0];

    // --- last block: deterministic final reduction over 256 partials ---
    __threadfence();
    if (u == 0) s_last = (atomicAdd(&g_done, 1) == gridDim.x - 1);
    __syncthreads();
    if (s_last) {
        __threadfence();
        volatile float* gp = (volatile float*)g_partial;
        s_red[u] = gp[u];
        __syncthreads();
        for (int s = 128; s > 0; s >>= 1) {
            if (u < s) s_red[u] += s_red[u + s];
            __syncthreads();
        }
        if (u == 0) {
            out[0] = s_red[0] * 0.2390057361376673f;   // kJ/mol -> kcal/mol
            g_done = 0;                                 // reset for replay
        }
    }
}

// ---------------------------------------------------------------------------
extern "C" void kernel_launch(void* const* d_in, const int* in_sizes, int n_in,
                              void* d_out, int out_size) {
    const float* pos   = (const float*)d_in[0];
    const int*   types = (const int*)d_in[1];
    const float* emb   = (const float*)d_in[2];
    const float* W1    = (const float*)d_in[3];
    const float* w2    = (const float*)d_in[4];
    float*       out   = (float*)d_out;

    k_prep <<<NA / 256, 256>>>(pos);
    k_build<<<1, 1024>>>();
    k_agg  <<<NCELL, 128>>>(emb, types);
    k_mlp  <<<NBLK_M, 256>>>(W1, w2, out);
}

// round 9
// speedup vs baseline: 1.4472x; 1.2094x over previous
#include <cuda_runtime.h>
#include <cuda_bf16.h>
#include <mma.h>
#include <cstdint>

using namespace nvcuda;

#define NA      8192
#define DD      128
#define HH      256
#define NC1     12          // cells per dimension (box 60 A / cutoff 5 A)
#define NCELL   (NC1*NC1*NC1)
#define MAXC    512         // max candidate atoms across 27 cells
#define MAXN    96          // max hits per atom (mean ~21)
#define BMT     64          // mlp block tile M
#define BNT     64          // mlp block tile N
#define NBLK    ((NA/BMT)*(HH/BNT))   // 128*4 = 512 mlp blocks
#define LDS_AB  72          // padded smem leading dim (bf16)
#define LDS_AC  68          // padded epilogue leading dim (f32)

typedef unsigned long long u64;

// ---- Scratch (static __device__ — no allocation) ---------------------------
__device__ float4        g_pos4[NA];
__device__ int           g_cellid[NA];
__device__ int           g_start[NCELL + 1];
__device__ int           g_slot[NA];
__device__ __nv_bfloat16 g_Ahi[NA * HH];    // feat hi, row-major [8192][256]
__device__ __nv_bfloat16 g_Alo[NA * HH];    // feat lo
__device__ __nv_bfloat16 g_Bhi[HH * HH];    // W1 hi,  row-major [256][256]
__device__ __nv_bfloat16 g_Blo[HH * HH];    // W1 lo
__device__ float         g_partial[NBLK];
__device__ int           g_done = 0;

// bf16 two-term split: v ~= hi + lo, each bf16 (lo = rounding residual)
__device__ __forceinline__ void bf16_split(float v, __nv_bfloat16& h,
                                           __nv_bfloat16& l) {
    h = __float2bfloat16(v);
    l = __float2bfloat16(__fadd_rn(v, -__bfloat162float(h)));
}

// ---------------------------------------------------------------------------
// Prep: nm -> angstrom; s = ((x*x)+(y*y))+(z*z) with NO fma contraction
// (matches XLA's elementwise/reduce rounding). Also compute 5A cell id.
// ---------------------------------------------------------------------------
__global__ void k_prep(const float* __restrict__ pos) {
    int i = blockIdx.x * 256 + threadIdx.x;
    if (i < NA) {
        float x = __fmul_rn(10.0f, pos[3 * i + 0]);
        float y = __fmul_rn(10.0f, pos[3 * i + 1]);
        float z = __fmul_rn(10.0f, pos[3 * i + 2]);
        float s = __fadd_rn(__fadd_rn(__fmul_rn(x, x), __fmul_rn(y, y)),
                            __fmul_rn(z, z));
        g_pos4[i] = make_float4(x, y, z, s);
        int cx = min(NC1 - 1, max(0, (int)(x * 0.2f)));
        int cy = min(NC1 - 1, max(0, (int)(y * 0.2f)));
        int cz = min(NC1 - 1, max(0, (int)(z * 0.2f)));
        g_cellid[i] = (cz * NC1 + cy) * NC1 + cx;
    }
}

// ---------------------------------------------------------------------------
// W1 bf16 split, row-major [K][N].
// ---------------------------------------------------------------------------
__global__ void k_wsplit(const float* __restrict__ W1) {
    int idx = blockIdx.x * 256 + threadIdx.x;     // 65536 total
    __nv_bfloat16 h, l;
    bf16_split(W1[idx], h, l);
    g_Bhi[idx] = h;
    g_Blo[idx] = l;
}

// ---------------------------------------------------------------------------
// Binning: histogram + scan + scatter + per-cell sort (single block).
// ---------------------------------------------------------------------------
__global__ void __launch_bounds__(1024) k_build() {
    __shared__ int a[2048], b[2048];
    __shared__ int cur[NCELL];
    const int t = threadIdx.x;

    if (t < NCELL - 1024) cur[1024 + t] = 0;
    cur[t] = 0;
    __syncthreads();

    int myc[8];
    #pragma unroll
    for (int k = 0; k < 8; k++) {
        myc[k] = g_cellid[t * 8 + k];
        atomicAdd(&cur[myc[k]], 1);
    }
    __syncthreads();

    #pragma unroll
    for (int k = 0; k < 2; k++) {
        int idx = t + 1024 * k;
        a[idx] = (idx < NCELL) ? cur[idx] : 0;
    }
    __syncthreads();
    int* src = a; int* dst = b;
    for (int s = 1; s < 2048; s <<= 1) {
        #pragma unroll
        for (int k = 0; k < 2; k++) {
            int idx = t + 1024 * k;
            int v = src[idx];
            if (idx >= s) v += src[idx - s];
            dst[idx] = v;
        }
        __syncthreads();
        int* tmp = src; src = dst; dst = tmp;
    }

    #pragma unroll
    for (int k = 0; k < 2; k++) {
        int idx = t + 1024 * k;
        if (idx < NCELL) {
            int st = src[idx] - cur[idx];
            g_start[idx] = st;
            cur[idx] = st;
        }
    }
    if (t == 0) g_start[NCELL] = NA;
    __syncthreads();

    #pragma unroll
    for (int k = 0; k < 8; k++) {
        int slot = atomicAdd(&cur[myc[k]], 1);
        g_slot[slot] = t * 8 + k;
    }
    __syncthreads();

    for (int c = t; c < NCELL; c += 1024) {
        int st = g_start[c], en = g_start[c + 1];
        for (int i = st + 1; i < en; i++) {
            int v = g_slot[i];
            int j = i - 1;
            while (j >= st && g_slot[j] > v) { g_slot[j + 1] = g_slot[j]; j--; }
            g_slot[j + 1] = v;
        }
    }
}

// ---------------------------------------------------------------------------
// Per-CELL radius graph + aggregation (pair math bit-exact vs reference);
// feat written as row-major bf16 hi/lo split matrices for the wmma GEMM.
// ---------------------------------------------------------------------------
__global__ void __launch_bounds__(128) k_agg(const float* __restrict__ emb,
                                             const int* __restrict__ types) {
    __shared__ float4 s_cpos[MAXC];
    __shared__ int    s_ctyp[MAXC];
    __shared__ float  s_phi [MAXN];
    __shared__ int    s_typ [MAXN];
    __shared__ int    s_gst [27];
    __shared__ int    s_coff[28];
    __shared__ int    s_wc  [4];

    const int tl = threadIdx.x;
    const int c  = blockIdx.x;
    const int cx = c % NC1, cy = (c / NC1) % NC1, cz = c / (NC1 * NC1);

    if (tl < 27) {
        int nx = cx + tl % 3 - 1;
        int ny = cy + (tl / 3) % 3 - 1;
        int nz = cz + tl / 9 - 1;
        int valid = (nx >= 0) & (nx < NC1) & (ny >= 0) & (ny < NC1)
                  & (nz >= 0) & (nz < NC1);
        int st = 0, cnt = 0;
        if (valid) {
            int nc = (nz * NC1 + ny) * NC1 + nx;
            st  = g_start[nc];
            cnt = g_start[nc + 1] - st;
        }
        s_gst[tl]  = st;
        s_coff[tl] = cnt;
    }
    __syncthreads();
    if (tl == 0) {
        int run = 0;
        #pragma unroll 1
        for (int q = 0; q < 27; q++) { int v = s_coff[q]; s_coff[q] = run; run += v; }
        s_coff[27] = run;
    }
    __syncthreads();

    const int ncand = s_coff[27];
    for (int p = tl; p < ncand; p += 128) {
        int q = 0;
        while (s_coff[q + 1] <= p) q++;
        int slot = s_gst[q] + (p - s_coff[q]);
        int a2   = g_slot[slot];
        s_cpos[p] = g_pos4[a2];
        s_ctyp[p] = types[a2];
    }
    __syncthreads();

    const int hbase = s_coff[13];
    const int nhome = s_coff[14] - s_coff[13];
    const int hst   = s_gst[13];
    const int wid = tl >> 5, lane = tl & 31;
    const unsigned lmask = (1u << lane) - 1u;

    for (int ha = 0; ha < nhome; ha++) {
        const float4 pi = s_cpos[hbase + ha];

        int nh = 0;
        for (int base = 0; base < ncand; base += 128) {
            int idx  = base + tl;
            int pred = 0, typ = 0;
            float phi = 0.0f;
            if (idx < ncand) {
                float4 pj = s_cpos[idx];
                float dot = __fmul_rn(pi.x, pj.x);
                dot = fmaf(pi.y, pj.y, dot);
                dot = fmaf(pi.z, pj.z, dot);
                float t1 = __fadd_rn(pi.w, pj.w);
                float d2 = __fadd_rn(t1, __fmul_rn(-2.0f, dot));
                if (d2 > 1e-12f) {
                    float d = __fsqrt_rn(d2);
                    if (d <= 5.0f) { pred = 1; phi = expf(-d); typ = s_ctyp[idx]; }
                }
            }
            unsigned m = __ballot_sync(0xffffffffu, pred);
            if (lane == 0) s_wc[wid] = __popc(m);
            __syncthreads();
            int woff = 0;
            #pragma unroll
            for (int w = 0; w < 4; w++) if (w < wid) woff += s_wc[w];
            if (pred) {
                int posn = nh + woff + __popc(m & lmask);
                if (posn < MAXN) { s_phi[posn] = phi; s_typ[posn] = typ; }
            }
            nh += s_wc[0] + s_wc[1] + s_wc[2] + s_wc[3];
            __syncthreads();
        }

        float acc = 0.0f;
        #pragma unroll 4
        for (int e = 0; e < nh; e++)
            acc = fmaf(s_phi[e], emb[s_typ[e] * DD + tl], acc);

        const int i = g_slot[hst + ha];
        __nv_bfloat16 h, l;
        bf16_split(emb[s_ctyp[hbase + ha] * DD + tl], h, l);
        g_Ahi[i * HH + tl] = h;  g_Alo[i * HH + tl] = l;
        bf16_split(acc, h, l);
        g_Ahi[i * HH + 128 + tl] = h;  g_Alo[i * HH + 128 + tl] = l;
        __syncthreads();
    }
}

// ---------------------------------------------------------------------------
// MLP on wmma bf16 two-term split GEMM (tensor pipe, base sm feature set).
// Block tile 64x64, 4 warps (warp tile 32x32 = 2x2 m16n16k16 frags).
// K staged in 64-chunks; 3 split products (hi*hi, hi*lo, lo*hi) accumulated
// into the same fp32 fragments. Epilogue: relu * w2, deterministic tree
// reduce, fused last-block final reduction.
// ---------------------------------------------------------------------------
__global__ void __launch_bounds__(128) k_mlp(const float* __restrict__ w2,
                                             float* __restrict__ out) {
    __shared__ __align__(16) __nv_bfloat16 s_stage[4 * 64 * LDS_AB];
    __shared__ float s_red[128];
    __shared__ int   s_last;

    __nv_bfloat16* sAhi = s_stage;
    __nv_bfloat16* sAlo = s_stage + 1 * 64 * LDS_AB;
    __nv_bfloat16* sBhi = s_stage + 2 * 64 * LDS_AB;
    __nv_bfloat16* sBlo = s_stage + 3 * 64 * LDS_AB;
    float* s_acc = (float*)s_stage;               // reused after mainloop

    const int tid  = threadIdx.x;
    const int wid  = tid >> 5;
    const int wm   = wid & 1, wn = wid >> 1;      // warp tile coords
    const int mt   = blockIdx.x >> 2, nt = blockIdx.x & 3;
    const int m0   = mt * BMT, n0 = nt * BNT;

    wmma::fragment<wmma::accumulator, 16, 16, 16, float> acc[2][2];
    #pragma unroll
    for (int i = 0; i < 2; i++)
        #pragma unroll
        for (int j = 0; j < 2; j++)
            wmma::fill_fragment(acc[i][j], 0.0f);

    #pragma unroll 1
    for (int kc = 0; kc < 4; kc++) {              // K chunks of 64
        __syncthreads();
        // stage Ahi/Alo rows [m0..m0+63] cols [64kc..+63], Bhi/Blo rows
        // [64kc..+63] cols [n0..+63]; 512 uint4 per array, 16 per thread
        #pragma unroll
        for (int j = tid; j < 512; j += 128) {
            int row = j >> 3, q = j & 7;
            *((uint4*)(sAhi + row * LDS_AB) + q) =
                *((const uint4*)(g_Ahi + (u64)(m0 + row) * HH + kc * 64) + q);
            *((uint4*)(sAlo + row * LDS_AB) + q) =
                *((const uint4*)(g_Alo + (u64)(m0 + row) * HH + kc * 64) + q);
            *((uint4*)(sBhi + row * LDS_AB) + q) =
                *((const uint4*)(g_Bhi + (u64)(kc * 64 + row) * HH + n0) + q);
            *((uint4*)(sBlo + row * LDS_AB) + q) =
                *((const uint4*)(g_Blo + (u64)(kc * 64 + row) * HH + n0) + q);
        }
        __syncthreads();

        #pragma unroll
        for (int sp = 0; sp < 3; sp++) {          // hi*hi, hi*lo, lo*hi
            const __nv_bfloat16* sA = (sp == 2) ? sAlo : sAhi;
            const __nv_bfloat16* sB = (sp == 1) ? sBlo : sBhi;
            #pragma unroll
            for (int ks = 0; ks < 4; ks++) {      // k16 steps in chunk
                wmma::fragment<wmma::matrix_a, 16, 16, 16, __nv_bfloat16,
                               wmma::row_major> af[2];
                wmma::fragment<wmma::matrix_b, 16, 16, 16, __nv_bfloat16,
                               wmma::row_major> bf[2];
                #pragma unroll
                for (int i = 0; i < 2; i++)
                    wmma::load_matrix_sync(
                        af[i], sA + (wm * 32 + i * 16) * LDS_AB + ks * 16,
                        LDS_AB);
                #pragma unroll
                for (int j = 0; j < 2; j++)
                    wmma::load_matrix_sync(
                        bf[j], sB + (ks * 16) * LDS_AB + wn * 32 + j * 16,
                        LDS_AB);
                #pragma unroll
                for (int i = 0; i < 2; i++)
                    #pragma unroll
                    for (int j = 0; j < 2; j++)
                        wmma::mma_sync(acc[i][j], af[i], bf[j], acc[i][j]);
            }
        }
    }
    __syncthreads();

    // epilogue: store 64x64 fp32 tile, relu * w2, fixed-order reduce
    #pragma unroll
    for (int i = 0; i < 2; i++)
        #pragma unroll
        for (int j = 0; j < 2; j++)
            wmma::store_matrix_sync(
                s_acc + (wm * 32 + i * 16) * LDS_AC + wn * 32 + j * 16,
                acc[i][j], LDS_AC, wmma::mem_row_major);
    __syncthreads();

    float p = 0.0f;
    #pragma unroll
    for (int e = 0; e < 32; e++) {
        int idx = tid + 128 * e;
        int row = idx >> 6, col = idx & 63;
        p += fmaxf(s_acc[row * LDS_AC + col], 0.0f) * __ldg(w2 + n0 + col);
    }
    s_red[tid] = p;
    __syncthreads();
    for (int s = 64; s > 0; s >>= 1) {
        if (tid < s) s_red[tid] += s_red[tid + s];
        __syncthreads();
    }
    if (tid == 0) g_partial[blockIdx.x] = s_red[0];

    // --- last block: deterministic final reduction over 512 partials ---
    __threadfence();
    if (tid == 0) s_last = (atomicAdd(&g_done, 1) == gridDim.x - 1);
    __syncthreads();
    if (s_last) {
        __threadfence();
        volatile float* gp = (volatile float*)g_partial;
        float q = 0.0f;
        #pragma unroll
        for (int e = 0; e < 4; e++) q += gp[tid + 128 * e];
        s_red[tid] = q;
        __syncthreads();
        for (int s = 64; s > 0; s >>= 1) {
            if (tid < s) s_red[tid] += s_red[tid + s];
            __syncthreads();
        }
        if (tid == 0) {
            out[0] = s_red[0] * 0.2390057361376673f;   // kJ/mol -> kcal/mol
            g_done = 0;                                 // reset for replay
        }
    }
}

// ---------------------------------------------------------------------------
extern "C" void kernel_launch(void* const* d_in, const int* in_sizes, int n_in,
                              void* d_out, int out_size) {
    const float* pos   = (const float*)d_in[0];
    const int*   types = (const int*)d_in[1];
    const float* emb   = (const float*)d_in[2];
    const float* W1    = (const float*)d_in[3];
    const float* w2    = (const float*)d_in[4];
    float*       out   = (float*)d_out;

    k_prep  <<<NA / 256, 256>>>(pos);
    k_wsplit<<<256, 256>>>(W1);
    k_build <<<1, 1024>>>();
    k_agg   <<<NCELL, 128>>>(emb, types);
    k_mlp   <<<NBLK, 128>>>(w2, out);
}

// round 10
// speedup vs baseline: 1.8193x; 1.2571x over previous
#include <cuda_runtime.h>
#include <cuda_bf16.h>
#include <mma.h>
#include <cstdint>

using namespace nvcuda;

#define NA      8192
#define DD      128
#define HH      256
#define NC1     12          // cells per dimension (box 60 A / cutoff 5 A)
#define NCELL   (NC1*NC1*NC1)
#define MAXC    320         // max candidate atoms across 27 cells (mean ~128)
#define BMT     64          // mlp block tile M
#define BNT     64          // mlp block tile N
#define NBLK    ((NA/BMT)*(HH/BNT))   // 512 mlp blocks
#define LDS_AB  72          // padded smem leading dim (bf16)
#define LDS_AC  68          // padded epilogue leading dim (f32)

typedef unsigned long long u64;

// ---- Scratch (static __device__ — no allocation) ---------------------------
__device__ float4        g_pos4[NA];
__device__ int           g_cellid[NA];
__device__ int           g_start[NCELL + 1];
__device__ int           g_slot[NA];
__device__ __nv_bfloat16 g_Ahi[NA * HH];    // feat hi, row-major [8192][256]
__device__ __nv_bfloat16 g_Alo[NA * HH];    // feat lo
__device__ __nv_bfloat16 g_Bhi[HH * HH];    // W1 hi,  row-major [256][256]
__device__ __nv_bfloat16 g_Blo[HH * HH];    // W1 lo
__device__ float         g_partial[NBLK];
__device__ int           g_done = 0;

// bf16 two-term split: v ~= hi + lo, each bf16 (lo = rounding residual)
__device__ __forceinline__ void bf16_split(float v, __nv_bfloat16& h,
                                           __nv_bfloat16& l) {
    h = __float2bfloat16(v);
    l = __float2bfloat16(__fadd_rn(v, -__bfloat162float(h)));
}

// split a float4 and store 4 bf16 (8 bytes) to hi/lo arrays
__device__ __forceinline__ void store_split4(__nv_bfloat16* hi,
                                             __nv_bfloat16* lo, float4 v) {
    __nv_bfloat162 h01, h23, l01, l23;
    __nv_bfloat16 h, l;
    bf16_split(v.x, h, l); h01.x = h; l01.x = l;
    bf16_split(v.y, h, l); h01.y = h; l01.y = l;
    bf16_split(v.z, h, l); h23.x = h; l23.x = l;
    bf16_split(v.w, h, l); h23.y = h; l23.y = l;
    ((__nv_bfloat162*)hi)[0] = h01;
    ((__nv_bfloat162*)hi)[1] = h23;
    ((__nv_bfloat162*)lo)[0] = l01;
    ((__nv_bfloat162*)lo)[1] = l23;
}

// ---------------------------------------------------------------------------
// Prep: nm -> angstrom; s = ((x*x)+(y*y))+(z*z) with NO fma contraction
// (matches XLA's elementwise/reduce rounding). Also compute 5A cell id.
// ---------------------------------------------------------------------------
__global__ void k_prep(const float* __restrict__ pos) {
    int i = blockIdx.x * 256 + threadIdx.x;
    if (i < NA) {
        float x = __fmul_rn(10.0f, pos[3 * i + 0]);
        float y = __fmul_rn(10.0f, pos[3 * i + 1]);
        float z = __fmul_rn(10.0f, pos[3 * i + 2]);
        float s = __fadd_rn(__fadd_rn(__fmul_rn(x, x), __fmul_rn(y, y)),
                            __fmul_rn(z, z));
        g_pos4[i] = make_float4(x, y, z, s);
        int cx = min(NC1 - 1, max(0, (int)(x * 0.2f)));
        int cy = min(NC1 - 1, max(0, (int)(y * 0.2f)));
        int cz = min(NC1 - 1, max(0, (int)(z * 0.2f)));
        g_cellid[i] = (cz * NC1 + cy) * NC1 + cx;
    }
}

// ---------------------------------------------------------------------------
// W1 bf16 split, row-major [K][N].
// ---------------------------------------------------------------------------
__global__ void k_wsplit(const float* __restrict__ W1) {
    int idx = blockIdx.x * 256 + threadIdx.x;     // 65536 total
    __nv_bfloat16 h, l;
    bf16_split(W1[idx], h, l);
    g_Bhi[idx] = h;
    g_Blo[idx] = l;
}

// ---------------------------------------------------------------------------
// Binning: histogram + scan + scatter + per-cell sort (single block).
// Sort stages each cell's slots into registers/local (independent loads)
// instead of pointer-chasing global insertion.
// ---------------------------------------------------------------------------
__global__ void __launch_bounds__(1024) k_build() {
    __shared__ int a[2048], b[2048];
    __shared__ int cur[NCELL];
    const int t = threadIdx.x;

    if (t < NCELL - 1024) cur[1024 + t] = 0;
    cur[t] = 0;
    __syncthreads();

    int myc[8];
    #pragma unroll
    for (int k = 0; k < 8; k++) {
        myc[k] = g_cellid[t * 8 + k];
        atomicAdd(&cur[myc[k]], 1);
    }
    __syncthreads();

    #pragma unroll
    for (int k = 0; k < 2; k++) {
        int idx = t + 1024 * k;
        a[idx] = (idx < NCELL) ? cur[idx] : 0;
    }
    __syncthreads();
    int* src = a; int* dst = b;
    for (int s = 1; s < 2048; s <<= 1) {
        #pragma unroll
        for (int k = 0; k < 2; k++) {
            int idx = t + 1024 * k;
            int v = src[idx];
            if (idx >= s) v += src[idx - s];
            dst[idx] = v;
        }
        __syncthreads();
        int* tmp = src; src = dst; dst = tmp;
    }

    #pragma unroll
    for (int k = 0; k < 2; k++) {
        int idx = t + 1024 * k;
        if (idx < NCELL) {
            int st = src[idx] - cur[idx];
            g_start[idx] = st;
            cur[idx] = st;
        }
    }
    if (t == 0) g_start[NCELL] = NA;
    __syncthreads();

    #pragma unroll
    for (int k = 0; k < 8; k++) {
        int slot = atomicAdd(&cur[myc[k]], 1);
        g_slot[slot] = t * 8 + k;
    }
    __syncthreads();

    for (int c = t; c < NCELL; c += 1024) {
        int st = g_start[c], en = g_start[c + 1];
        int cn = en - st;
        if (cn <= 32) {
            int loc[32];
            for (int i = 0; i < cn; i++) loc[i] = g_slot[st + i];
            for (int i = 1; i < cn; i++) {
                int v = loc[i], j = i - 1;
                while (j >= 0 && loc[j] > v) { loc[j + 1] = loc[j]; j--; }
                loc[j + 1] = v;
            }
            for (int i = 0; i < cn; i++) g_slot[st + i] = loc[i];
        } else {
            for (int i = st + 1; i < en; i++) {
                int v = g_slot[i], j = i - 1;
                while (j >= st && g_slot[j] > v) { g_slot[j+1] = g_slot[j]; j--; }
                g_slot[j + 1] = v;
            }
        }
    }
}

// ---------------------------------------------------------------------------
// Per-CELL radius graph + aggregation, WARP-INDEPENDENT home atoms.
// Block stages candidates once (2 barriers); then warp w processes home
// atoms w, w+4, ... with no further block syncs: 32-candidate test rounds,
// ballot + ffs/shfl hit broadcast (ascending candidate order — identical
// summation order to the compacted version), lane l owns feature components
// 4l..4l+3 (single LDG.128 per hit). Pair math bit-exact vs reference:
//   dot = fma(z,z, fma(y,y, x*x));  d2 = RN(RN(s_i+s_j) - 2*dot)
// ---------------------------------------------------------------------------
__global__ void __launch_bounds__(128) k_agg(const float* __restrict__ emb,
                                             const int* __restrict__ types) {
    __shared__ float4        s_cpos[MAXC];
    __shared__ int           s_ctyp[MAXC];
    __shared__ unsigned char s_cmap[MAXC];
    __shared__ int           s_gst[32];
    __shared__ int           s_coff[33];

    const int tl   = threadIdx.x;
    const int lane = tl & 31, w = tl >> 5;
    const int c  = blockIdx.x;
    const int cx = c % NC1, cy = (c / NC1) % NC1, cz = c / (NC1 * NC1);

    // --- warp 0: extents + shfl prefix scan + cell map fill ---
    if (tl < 32) {
        int st = 0, cnt = 0;
        if (tl < 27) {
            int nx = cx + tl % 3 - 1;
            int ny = cy + (tl / 3) % 3 - 1;
            int nz = cz + tl / 9 - 1;
            if (nx >= 0 && nx < NC1 && ny >= 0 && ny < NC1 &&
                nz >= 0 && nz < NC1) {
                int nc = (nz * NC1 + ny) * NC1 + nx;
                st  = g_start[nc];
                cnt = g_start[nc + 1] - st;
            }
        }
        s_gst[tl] = st;
        int v = cnt;
        #pragma unroll
        for (int o = 1; o < 32; o <<= 1) {
            int u2 = __shfl_up_sync(0xffffffffu, v, o);
            if (lane >= o) v += u2;
        }
        s_coff[tl + 1] = v;
        if (tl == 0) s_coff[0] = 0;
        int off = v - cnt;
        for (int q = 0; q < cnt; q++)
            s_cmap[off + q] = (unsigned char)tl;
    }
    __syncthreads();

    const int ncand = s_coff[27];
    const int hbase = s_coff[13];
    const int nhome = s_coff[14] - s_coff[13];
    const int hst   = s_gst[13];
    if (nhome == 0) return;

    // --- parallel candidate staging (direct cell map, one round) ---
    for (int p = tl; p < ncand; p += 128) {
        int q    = s_cmap[p];
        int slot = s_gst[q] + (p - s_coff[q]);
        int a2   = g_slot[slot];
        s_cpos[p] = g_pos4[a2];
        s_ctyp[p] = types[a2];
    }
    __syncthreads();

    // --- per-warp independent home-atom processing (no block syncs) ---
    for (int ha = w; ha < nhome; ha += 4) {
        const float4 pi = s_cpos[hbase + ha];
        float4 acc = make_float4(0.f, 0.f, 0.f, 0.f);

        for (int base = 0; base < ncand; base += 32) {
            int k = base + lane;
            int pred = 0, typ = 0;
            float phi = 0.0f;
            if (k < ncand) {
                float4 pj = s_cpos[k];
                float dot = __fmul_rn(pi.x, pj.x);
                dot = fmaf(pi.y, pj.y, dot);
                dot = fmaf(pi.z, pj.z, dot);
                float t1 = __fadd_rn(pi.w, pj.w);
                float d2 = __fadd_rn(t1, __fmul_rn(-2.0f, dot));
                if (d2 > 1e-12f) {
                    float d = __fsqrt_rn(d2);
                    if (d <= 5.0f) { pred = 1; phi = expf(-d); typ = s_ctyp[k]; }
                }
            }
            unsigned m = __ballot_sync(0xffffffffu, pred);
            while (m) {                         // ascending lane = cand order
                int srcl = __ffs(m) - 1;
                m &= m - 1;
                float ph = __shfl_sync(0xffffffffu, phi, srcl);
                int   ty = __shfl_sync(0xffffffffu, typ, srcl);
                float4 ev = *(const float4*)(emb + ty * DD + lane * 4);
                acc.x = fmaf(ph, ev.x, acc.x);
                acc.y = fmaf(ph, ev.y, acc.y);
                acc.z = fmaf(ph, ev.z, acc.z);
                acc.w = fmaf(ph, ev.w, acc.w);
            }
        }

        const int i  = g_slot[hst + ha];        // original atom index
        const int ti = s_ctyp[hbase + ha];
        float4 hv = *(const float4*)(emb + ti * DD + lane * 4);
        store_split4(g_Ahi + (u64)i * HH + lane * 4,
                     g_Alo + (u64)i * HH + lane * 4, hv);
        store_split4(g_Ahi + (u64)i * HH + 128 + lane * 4,
                     g_Alo + (u64)i * HH + 128 + lane * 4, acc);
    }
}

// ---------------------------------------------------------------------------
// MLP on wmma bf16 two-term split GEMM (unchanged from round 8).
// ---------------------------------------------------------------------------
__global__ void __launch_bounds__(128) k_mlp(const float* __restrict__ w2,
                                             float* __restrict__ out) {
    __shared__ __align__(16) __nv_bfloat16 s_stage[4 * 64 * LDS_AB];
    __shared__ float s_red[128];
    __shared__ int   s_last;

    __nv_bfloat16* sAhi = s_stage;
    __nv_bfloat16* sAlo = s_stage + 1 * 64 * LDS_AB;
    __nv_bfloat16* sBhi = s_stage + 2 * 64 * LDS_AB;
    __nv_bfloat16* sBlo = s_stage + 3 * 64 * LDS_AB;
    float* s_acc = (float*)s_stage;               // reused after mainloop

    const int tid  = threadIdx.x;
    const int wid  = tid >> 5;
    const int wm   = wid & 1, wn = wid >> 1;
    const int mt   = blockIdx.x >> 2, nt = blockIdx.x & 3;
    const int m0   = mt * BMT, n0 = nt * BNT;

    wmma::fragment<wmma::accumulator, 16, 16, 16, float> acc[2][2];
    #pragma unroll
    for (int i = 0; i < 2; i++)
        #pragma unroll
        for (int j = 0; j < 2; j++)
            wmma::fill_fragment(acc[i][j], 0.0f);

    #pragma unroll 1
    for (int kc = 0; kc < 4; kc++) {
        __syncthreads();
        #pragma unroll
        for (int j = tid; j < 512; j += 128) {
            int row = j >> 3, q = j & 7;
            *((uint4*)(sAhi + row * LDS_AB) + q) =
                *((const uint4*)(g_Ahi + (u64)(m0 + row) * HH + kc * 64) + q);
            *((uint4*)(sAlo + row * LDS_AB) + q) =
                *((const uint4*)(g_Alo + (u64)(m0 + row) * HH + kc * 64) + q);
            *((uint4*)(sBhi + row * LDS_AB) + q) =
                *((const uint4*)(g_Bhi + (u64)(kc * 64 + row) * HH + n0) + q);
            *((uint4*)(sBlo + row * LDS_AB) + q) =
                *((const uint4*)(g_Blo + (u64)(kc * 64 + row) * HH + n0) + q);
        }
        __syncthreads();

        #pragma unroll
        for (int sp = 0; sp < 3; sp++) {          // hi*hi, hi*lo, lo*hi
            const __nv_bfloat16* sA = (sp == 2) ? sAlo : sAhi;
            const __nv_bfloat16* sB = (sp == 1) ? sBlo : sBhi;
            #pragma unroll
            for (int ks = 0; ks < 4; ks++) {
                wmma::fragment<wmma::matrix_a, 16, 16, 16, __nv_bfloat16,
                               wmma::row_major> af[2];
                wmma::fragment<wmma::matrix_b, 16, 16, 16, __nv_bfloat16,
                               wmma::row_major> bf[2];
                #pragma unroll
                for (int i = 0; i < 2; i++)
                    wmma::load_matrix_sync(
                        af[i], sA + (wm * 32 + i * 16) * LDS_AB + ks * 16,
                        LDS_AB);
                #pragma unroll
                for (int j = 0; j < 2; j++)
                    wmma::load_matrix_sync(
                        bf[j], sB + (ks * 16) * LDS_AB + wn * 32 + j * 16,
                        LDS_AB);
                #pragma unroll
                for (int i = 0; i < 2; i++)
                    #pragma unroll
                    for (int j = 0; j < 2; j++)
                        wmma::mma_sync(acc[i][j], af[i], bf[j], acc[i][j]);
            }
        }
    }
    __syncthreads();

    #pragma unroll
    for (int i = 0; i < 2; i++)
        #pragma unroll
        for (int j = 0; j < 2; j++)
            wmma::store_matrix_sync(
                s_acc + (wm * 32 + i * 16) * LDS_AC + wn * 32 + j * 16,
                acc[i][j], LDS_AC, wmma::mem_row_major);
    __syncthreads();

    float p = 0.0f;
    #pragma unroll
    for (int e = 0; e < 32; e++) {
        int idx = tid + 128 * e;
        int row = idx >> 6, col = idx & 63;
        p += fmaxf(s_acc[row * LDS_AC + col], 0.0f) * __ldg(w2 + n0 + col);
    }
    s_red[tid] = p;
    __syncthreads();
    for (int s = 64; s > 0; s >>= 1) {
        if (tid < s) s_red[tid] += s_red[tid + s];
        __syncthreads();
    }
    if (tid == 0) g_partial[blockIdx.x] = s_red[0];

    __threadfence();
    if (tid == 0) s_last = (atomicAdd(&g_done, 1) == gridDim.x - 1);
    __syncthreads();
    if (s_last) {
        __threadfence();
        volatile float* gp = (volatile float*)g_partial;
        float q = 0.0f;
        #pragma unroll
        for (int e = 0; e < 4; e++) q += gp[tid + 128 * e];
        s_red[tid] = q;
        __syncthreads();
        for (int s = 64; s > 0; s >>= 1) {
            if (tid < s) s_red[tid] += s_red[tid + s];
            __syncthreads();
        }
        if (tid == 0) {
            out[0] = s_red[0] * 0.2390057361376673f;   // kJ/mol -> kcal/mol
            g_done = 0;                                 // reset for replay
        }
    }
}

// ---------------------------------------------------------------------------
extern "C" void kernel_launch(void* const* d_in, const int* in_sizes, int n_in,
                              void* d_out, int out_size) {
    const float* pos   = (const float*)d_in[0];
    const int*   types = (const int*)d_in[1];
    const float* emb   = (const float*)d_in[2];
    const float* W1    = (const float*)d_in[3];
    const float* w2    = (const float*)d_in[4];
    float*       out   = (float*)d_out;

    k_prep  <<<NA / 256, 256>>>(pos);
    k_wsplit<<<256, 256>>>(W1);
    k_build <<<1, 1024>>>();
    k_agg   <<<NCELL, 128>>>(emb, types);
    k_mlp   <<<NBLK, 128>>>(w2, out);
}

// round 11
// speedup vs baseline: 1.9395x; 1.0660x over previous
#include <cuda_runtime.h>
#include <cuda_bf16.h>
#include <mma.h>
#include <cstdint>

using namespace nvcuda;

#define NA      8192
#define DD      128
#define HH      256
#define NC1     12          // cells per dimension (box 60 A / cutoff 5 A)
#define NCELL   (NC1*NC1*NC1)
#define MAXC    320         // max candidate atoms across 27 cells (mean ~128)
#define BMT     64          // mlp block tile M
#define BNT     64          // mlp block tile N
#define NBLK    ((NA/BMT)*(HH/BNT))   // 512 mlp blocks
#define LDS_AB  72          // padded smem leading dim (bf16)
#define LDS_AC  68          // padded epilogue leading dim (f32)

typedef unsigned long long u64;

// ---- Scratch (static __device__ — no allocation) ---------------------------
__device__ float4        g_pos4[NA];
__device__ int           g_cellid[NA];
__device__ int           g_count[NCELL];
__device__ int           g_cursor[NCELL];
__device__ int           g_start[NCELL + 1];
__device__ int           g_slot[NA];       // cell-sorted original atom indices
__device__ float4        g_spos[NA];       // cell-sorted positions
__device__ int           g_stype[NA];      // cell-sorted types
__device__ __nv_bfloat16 g_Ahi[NA * HH];   // feat hi, row-major [8192][256]
__device__ __nv_bfloat16 g_Alo[NA * HH];   // feat lo
__device__ __nv_bfloat16 g_Bhi[HH * HH];   // W1 hi,  row-major [256][256]
__device__ __nv_bfloat16 g_Blo[HH * HH];   // W1 lo
__device__ float         g_partial[NBLK];
__device__ int           g_done = 0;

// bf16 two-term split: v ~= hi + lo, each bf16 (lo = rounding residual)
__device__ __forceinline__ void bf16_split(float v, __nv_bfloat16& h,
                                           __nv_bfloat16& l) {
    h = __float2bfloat16(v);
    l = __float2bfloat16(__fadd_rn(v, -__bfloat162float(h)));
}

__device__ __forceinline__ void store_split4(__nv_bfloat16* hi,
                                             __nv_bfloat16* lo, float4 v) {
    __nv_bfloat162 h01, h23, l01, l23;
    __nv_bfloat16 h, l;
    bf16_split(v.x, h, l); h01.x = h; l01.x = l;
    bf16_split(v.y, h, l); h01.y = h; l01.y = l;
    bf16_split(v.z, h, l); h23.x = h; l23.x = l;
    bf16_split(v.w, h, l); h23.y = h; l23.y = l;
    ((__nv_bfloat162*)hi)[0] = h01;
    ((__nv_bfloat162*)hi)[1] = h23;
    ((__nv_bfloat162*)lo)[0] = l01;
    ((__nv_bfloat162*)lo)[1] = l23;
}

// ---------------------------------------------------------------------------
// W1 bf16 split, row-major [K][N]. Also zeroes the cell histogram (runs
// before k_prep's counting atomics in stream order).
// ---------------------------------------------------------------------------
__global__ void k_wsplit(const float* __restrict__ W1) {
    int idx = blockIdx.x * 256 + threadIdx.x;     // 65536 total
    __nv_bfloat16 h, l;
    bf16_split(W1[idx], h, l);
    g_Bhi[idx] = h;
    g_Blo[idx] = l;
    if (idx < NCELL) g_count[idx] = 0;
}

// ---------------------------------------------------------------------------
// Prep: nm -> angstrom; s = ((x*x)+(y*y))+(z*z) with NO fma contraction
// (matches XLA's elementwise/reduce rounding). Cell id + global histogram.
// ---------------------------------------------------------------------------
__global__ void k_prep(const float* __restrict__ pos) {
    int i = blockIdx.x * 256 + threadIdx.x;
    if (i < NA) {
        float x = __fmul_rn(10.0f, pos[3 * i + 0]);
        float y = __fmul_rn(10.0f, pos[3 * i + 1]);
        float z = __fmul_rn(10.0f, pos[3 * i + 2]);
        float s = __fadd_rn(__fadd_rn(__fmul_rn(x, x), __fmul_rn(y, y)),
                            __fmul_rn(z, z));
        g_pos4[i] = make_float4(x, y, z, s);
        int cx = min(NC1 - 1, max(0, (int)(x * 0.2f)));
        int cy = min(NC1 - 1, max(0, (int)(y * 0.2f)));
        int cz = min(NC1 - 1, max(0, (int)(z * 0.2f)));
        int c  = (cz * NC1 + cy) * NC1 + cx;
        g_cellid[i] = c;
        atomicAdd(&g_count[c], 1);
    }
}

// ---------------------------------------------------------------------------
// Exclusive scan over 1728 cell counts (1 block); init cursors + sentinel.
// ---------------------------------------------------------------------------
__global__ void __launch_bounds__(1024) k_scan() {
    __shared__ int a[2048], b[2048];
    const int t = threadIdx.x;
    #pragma unroll
    for (int k = 0; k < 2; k++) {
        int idx = t + 1024 * k;
        a[idx] = (idx < NCELL) ? g_count[idx] : 0;
    }
    __syncthreads();
    int* src = a; int* dst = b;
    for (int s = 1; s < 2048; s <<= 1) {
        #pragma unroll
        for (int k = 0; k < 2; k++) {
            int idx = t + 1024 * k;
            int v = src[idx];
            if (idx >= s) v += src[idx - s];
            dst[idx] = v;
        }
        __syncthreads();
        int* tmp = src; src = dst; dst = tmp;
    }
    #pragma unroll
    for (int k = 0; k < 2; k++) {
        int idx = t + 1024 * k;
        if (idx < NCELL) {
            int st = src[idx] - g_count[idx];
            g_start[idx]  = st;
            g_cursor[idx] = st;
        }
    }
    if (t == 0) g_start[NCELL] = NA;
}

// ---------------------------------------------------------------------------
__global__ void k_scatter() {
    int i = blockIdx.x * 256 + threadIdx.x;
    if (i < NA) {
        int slot = atomicAdd(&g_cursor[g_cellid[i]], 1);
        g_slot[slot] = i;
    }
}

// ---------------------------------------------------------------------------
// Per-cell: sort slots ascending (deterministic order) + gather pos/type.
// One thread per cell, fully parallel across blocks.
// ---------------------------------------------------------------------------
__global__ void k_sortgather(const int* __restrict__ types) {
    int c = blockIdx.x * 256 + threadIdx.x;
    if (c < NCELL) {
        int st = g_start[c], en = g_start[c + 1];
        int cn = en - st;
        int loc[32];
        if (cn > 32) cn = 32;                    // statistically unreachable
        for (int i = 0; i < cn; i++) loc[i] = g_slot[st + i];
        for (int i = 1; i < cn; i++) {
            int v = loc[i], j = i - 1;
            while (j >= 0 && loc[j] > v) { loc[j + 1] = loc[j]; j--; }
            loc[j + 1] = v;
        }
        for (int i = 0; i < cn; i++) {
            int a = loc[i];
            g_slot[st + i]  = a;
            g_spos[st + i]  = g_pos4[a];
            g_stype[st + i] = types[a];
        }
    }
}

// ---------------------------------------------------------------------------
// Per-CELL radius graph + aggregation, warp-independent home atoms.
// NEW: d2 <= 25.01f prefilter — provably includes every candidate the
// reference's (d = sqrt_rn(d2)) <= 5.0 test can accept (sqrt monotone,
// sqrt(25.01)(1-2^-24) > 5.0), so sqrt/exp run only on ~hits; the exact
// test is still applied inside. Pair math bit-exact vs reference:
//   dot = fma(z,z, fma(y,y, x*x));  d2 = RN(RN(s_i+s_j) - 2*dot)
// ---------------------------------------------------------------------------
__global__ void __launch_bounds__(128) k_agg(const float* __restrict__ emb) {
    __shared__ float4        s_cpos[MAXC];
    __shared__ int           s_ctyp[MAXC];
    __shared__ unsigned char s_cmap[MAXC];
    __shared__ int           s_gst[32];
    __shared__ int           s_coff[33];

    const int tl   = threadIdx.x;
    const int lane = tl & 31, w = tl >> 5;
    const int c  = blockIdx.x;
    const int cx = c % NC1, cy = (c / NC1) % NC1, cz = c / (NC1 * NC1);

    // --- warp 0: extents + shfl prefix scan + cell map fill ---
    if (tl < 32) {
        int st = 0, cnt = 0;
        if (tl < 27) {
            int nx = cx + tl % 3 - 1;
            int ny = cy + (tl / 3) % 3 - 1;
            int nz = cz + tl / 9 - 1;
            if (nx >= 0 && nx < NC1 && ny >= 0 && ny < NC1 &&
                nz >= 0 && nz < NC1) {
                int nc = (nz * NC1 + ny) * NC1 + nx;
                st  = g_start[nc];
                cnt = g_start[nc + 1] - st;
            }
        }
        s_gst[tl] = st;
        int v = cnt;
        #pragma unroll
        for (int o = 1; o < 32; o <<= 1) {
            int u2 = __shfl_up_sync(0xffffffffu, v, o);
            if (lane >= o) v += u2;
        }
        s_coff[tl + 1] = v;
        if (tl == 0) s_coff[0] = 0;
        int off = v - cnt;
        for (int q = 0; q < cnt; q++)
            s_cmap[off + q] = (unsigned char)tl;
    }
    __syncthreads();

    const int ncand = s_coff[27];
    const int hbase = s_coff[13];
    const int nhome = s_coff[14] - s_coff[13];
    const int hst   = s_gst[13];
    if (nhome == 0) return;

    // --- parallel candidate staging (single load level via g_spos) ---
    for (int p = tl; p < ncand; p += 128) {
        int q    = s_cmap[p];
        int slot = s_gst[q] + (p - s_coff[q]);
        s_cpos[p] = g_spos[slot];
        s_ctyp[p] = g_stype[slot];
    }
    __syncthreads();

    // --- per-warp independent home-atom processing (no block syncs) ---
    for (int ha = w; ha < nhome; ha += 4) {
        const float4 pi = s_cpos[hbase + ha];
        float4 acc = make_float4(0.f, 0.f, 0.f, 0.f);

        for (int base = 0; base < ncand; base += 32) {
            int k = base + lane;
            int pred = 0, typ = 0;
            float phi = 0.0f;
            if (k < ncand) {
                float4 pj = s_cpos[k];
                float dot = __fmul_rn(pi.x, pj.x);
                dot = fmaf(pi.y, pj.y, dot);
                dot = fmaf(pi.z, pj.z, dot);
                float t1 = __fadd_rn(pi.w, pj.w);
                float d2 = __fadd_rn(t1, __fmul_rn(-2.0f, dot));
                if (d2 > 1e-12f && d2 <= 25.01f) {       // cheap prefilter
                    float d = __fsqrt_rn(d2);
                    if (d <= 5.0f) {                      // exact ref test
                        pred = 1; phi = expf(-d); typ = s_ctyp[k];
                    }
                }
            }
            unsigned m = __ballot_sync(0xffffffffu, pred);
            while (m) {                          // ascending lane = cand order
                int srcl = __ffs(m) - 1;
                m &= m - 1;
                float ph = __shfl_sync(0xffffffffu, phi, srcl);
                int   ty = __shfl_sync(0xffffffffu, typ, srcl);
                float4 ev = *(const float4*)(emb + ty * DD + lane * 4);
                acc.x = fmaf(ph, ev.x, acc.x);
                acc.y = fmaf(ph, ev.y, acc.y);
                acc.z = fmaf(ph, ev.z, acc.z);
                acc.w = fmaf(ph, ev.w, acc.w);
            }
        }

        const int i  = g_slot[hst + ha];         // original atom index
        const int ti = s_ctyp[hbase + ha];
        float4 hv = *(const float4*)(emb + ti * DD + lane * 4);
        store_split4(g_Ahi + (u64)i * HH + lane * 4,
                     g_Alo + (u64)i * HH + lane * 4, hv);
        store_split4(g_Ahi + (u64)i * HH + 128 + lane * 4,
                     g_Alo + (u64)i * HH + 128 + lane * 4, acc);
    }
}

// ---------------------------------------------------------------------------
// MLP on wmma bf16 two-term split GEMM (unchanged).
// ---------------------------------------------------------------------------
__global__ void __launch_bounds__(128) k_mlp(const float* __restrict__ w2,
                                             float* __restrict__ out) {
    __shared__ __align__(16) __nv_bfloat16 s_stage[4 * 64 * LDS_AB];
    __shared__ float s_red[128];
    __shared__ int   s_last;

    __nv_bfloat16* sAhi = s_stage;
    __nv_bfloat16* sAlo = s_stage + 1 * 64 * LDS_AB;
    __nv_bfloat16* sBhi = s_stage + 2 * 64 * LDS_AB;
    __nv_bfloat16* sBlo = s_stage + 3 * 64 * LDS_AB;
    float* s_acc = (float*)s_stage;               // reused after mainloop

    const int tid  = threadIdx.x;
    const int wid  = tid >> 5;
    const int wm   = wid & 1, wn = wid >> 1;
    const int mt   = blockIdx.x >> 2, nt = blockIdx.x & 3;
    const int m0   = mt * BMT, n0 = nt * BNT;

    wmma::fragment<wmma::accumulator, 16, 16, 16, float> acc[2][2];
    #pragma unroll
    for (int i = 0; i < 2; i++)
        #pragma unroll
        for (int j = 0; j < 2; j++)
            wmma::fill_fragment(acc[i][j], 0.0f);

    #pragma unroll 1
    for (int kc = 0; kc < 4; kc++) {
        __syncthreads();
        #pragma unroll
        for (int j = tid; j < 512; j += 128) {
            int row = j >> 3, q = j & 7;
            *((uint4*)(sAhi + row * LDS_AB) + q) =
                *((const uint4*)(g_Ahi + (u64)(m0 + row) * HH + kc * 64) + q);
            *((uint4*)(sAlo + row * LDS_AB) + q) =
                *((const uint4*)(g_Alo + (u64)(m0 + row) * HH + kc * 64) + q);
            *((uint4*)(sBhi + row * LDS_AB) + q) =
                *((const uint4*)(g_Bhi + (u64)(kc * 64 + row) * HH + n0) + q);
            *((uint4*)(sBlo + row * LDS_AB) + q) =
                *((const uint4*)(g_Blo + (u64)(kc * 64 + row) * HH + n0) + q);
        }
        __syncthreads();

        #pragma unroll
        for (int sp = 0; sp < 3; sp++) {          // hi*hi, hi*lo, lo*hi
            const __nv_bfloat16* sA = (sp == 2) ? sAlo : sAhi;
            const __nv_bfloat16* sB = (sp == 1) ? sBlo : sBhi;
            #pragma unroll
            for (int ks = 0; ks < 4; ks++) {
                wmma::fragment<wmma::matrix_a, 16, 16, 16, __nv_bfloat16,
                               wmma::row_major> af[2];
                wmma::fragment<wmma::matrix_b, 16, 16, 16, __nv_bfloat16,
                               wmma::row_major> bf[2];
                #pragma unroll
                for (int i = 0; i < 2; i++)
                    wmma::load_matrix_sync(
                        af[i], sA + (wm * 32 + i * 16) * LDS_AB + ks * 16,
                        LDS_AB);
                #pragma unroll
                for (int j = 0; j < 2; j++)
                    wmma::load_matrix_sync(
                        bf[j], sB + (ks * 16) * LDS_AB + wn * 32 + j * 16,
                        LDS_AB);
                #pragma unroll
                for (int i = 0; i < 2; i++)
                    #pragma unroll
                    for (int j = 0; j < 2; j++)
                        wmma::mma_sync(acc[i][j], af[i], bf[j], acc[i][j]);
            }
        }
    }
    __syncthreads();

    #pragma unroll
    for (int i = 0; i < 2; i++)
        #pragma unroll
        for (int j = 0; j < 2; j++)
            wmma::store_matrix_sync(
                s_acc + (wm * 32 + i * 16) * LDS_AC + wn * 32 + j * 16,
                acc[i][j], LDS_AC, wmma::mem_row_major);
    __syncthreads();

    float p = 0.0f;
    #pragma unroll
    for (int e = 0; e < 32; e++) {
        int idx = tid + 128 * e;
        int row = idx >> 6, col = idx & 63;
        p += fmaxf(s_acc[row * LDS_AC + col], 0.0f) * __ldg(w2 + n0 + col);
    }
    s_red[tid] = p;
    __syncthreads();
    for (int s = 64; s > 0; s >>= 1) {
        if (tid < s) s_red[tid] += s_red[tid + s];
        __syncthreads();
    }
    if (tid == 0) g_partial[blockIdx.x] = s_red[0];

    __threadfence();
    if (tid == 0) s_last = (atomicAdd(&g_done, 1) == gridDim.x - 1);
    __syncthreads();
    if (s_last) {
        __threadfence();
        volatile float* gp = (volatile float*)g_partial;
        float q = 0.0f;
        #pragma unroll
        for (int e = 0; e < 4; e++) q += gp[tid + 128 * e];
        s_red[tid] = q;
        __syncthreads();
        for (int s = 64; s > 0; s >>= 1) {
            if (tid < s) s_red[tid] += s_red[tid + s];
            __syncthreads();
        }
        if (tid == 0) {
            out[0] = s_red[0] * 0.2390057361376673f;   // kJ/mol -> kcal/mol
            g_done = 0;                                 // reset for replay
        }
    }
}

// ---------------------------------------------------------------------------
extern "C" void kernel_launch(void* const* d_in, const int* in_sizes, int n_in,
                              void* d_out, int out_size) {
    const float* pos   = (const float*)d_in[0];
    const int*   types = (const int*)d_in[1];
    const float* emb   = (const float*)d_in[2];
    const float* W1    = (const float*)d_in[3];
    const float* w2    = (const float*)d_in[4];
    float*       out   = (float*)d_out;

    k_wsplit    <<<256, 256>>>(W1);            // also zeroes g_count
    k_prep      <<<NA / 256, 256>>>(pos);      // + histogram
    k_scan      <<<1, 1024>>>();
    k_scatter   <<<NA / 256, 256>>>();
    k_sortgather<<<(NCELL + 255) / 256, 256>>>(types);
    k_agg       <<<NCELL, 128>>>(emb);
    k_mlp       <<<NBLK, 128>>>(w2, out);
}